// round 16
// baseline (speedup 1.0000x reference)
#include <cuda_runtime.h>

#define BB 512
#define SS 1024
#define TT 48
#define MID 512
#define LN64 4.1588830833596715f

typedef unsigned long long u64;

__device__ float g_alpha[BB][TT];
__device__ float g_beta[BB][TT];
__device__ float g_cA[BB], g_cB[BB];
__device__ float g_gold[BB];        // gold path incl. end term
__device__ int   g_nmat[BB];        // applied matvec count (nA + 1 + nB)

__device__ __forceinline__ u64 ffma2(u64 a, u64 b, u64 c) {
    u64 d; asm("fma.rn.f32x2 %0, %1, %2, %3;" : "=l"(d) : "l"(a), "l"(b), "l"(c)); return d;
}
__device__ __forceinline__ u64 fmul2(u64 a, u64 b) {
    u64 d; asm("mul.rn.f32x2 %0, %1, %2;" : "=l"(d) : "l"(a), "l"(b)); return d;
}
__device__ __forceinline__ u64 fadd2(u64 a, u64 b) {
    u64 d; asm("add.rn.f32x2 %0, %1, %2;" : "=l"(d) : "l"(a), "l"(b)); return d;
}
__device__ __forceinline__ u64 pack2(float lo, float hi) {
    u64 d; asm("mov.b64 %0, {%1, %2};" : "=l"(d) : "f"(lo), "f"(hi)); return d;
}
__device__ __forceinline__ void unpack2(u64 v, float& lo, float& hi) {
    asm("mov.b64 {%0, %1}, %2;" : "=f"(lo), "=f"(hi) : "l"(v));
}

// ---------------------------------------------------------------------------
// Fused scan + gold. Blocks [0,512): forward halves; [512,1024): backward
// halves (validated R15 core, untouched); [1024,1536): gold-path gather, one
// warp per batch — memory-latency bound, hides in the scan's idle issue slots.
// ---------------------------------------------------------------------------
__global__ void __launch_bounds__(32) crf_fwdbwd(
    const float* __restrict__ em,       // [B,S,T]
    const float* __restrict__ trans,    // [T,T]
    const float* __restrict__ startt,   // [T]
    const float* __restrict__ endt,     // [T]
    const int* __restrict__ tags,       // [B,S]
    const int* __restrict__ mask)       // [B,S] bool as int32
{
    // ---------------- gold gather branch (blocks 1024..1535) ----------------
    if (blockIdx.x >= 2 * BB) {
        const int b = blockIdx.x - 2 * BB;
        const int lane = threadIdx.x;
        const int* tg = tags + (size_t)b * SS;
        const int* mk = mask + (size_t)b * SS;
        const float* emb = em + (size_t)b * SS * TT;

        float g = 0.0f;
        int cnt = 0, nA = 0, nB = 0;
        for (int t = lane; t < SS; t += 32) {
            const int mt = __ldg(&mk[t]) ? 1 : 0;
            cnt += mt;
            if (t == 0) {
                const int t0 = __ldg(&tg[0]);
                g += startt[t0] + __ldg(&emb[t0]);
            } else if (mt) {
                const int tc = __ldg(&tg[t]);
                const int tp = __ldg(&tg[t - 1]);
                g += __ldg(&trans[tp * TT + tc])
                   + __ldg(&emb[(size_t)t * TT + tc]);
                if (t <= MID) nA++; else if (t <= SS - 2) nB++;
            }
        }
        // deterministic fixed-order warp tree reduction
#pragma unroll
        for (int off = 16; off > 0; off >>= 1) {
            g   += __shfl_down_sync(0xffffffffu, g, off);
            cnt += __shfl_down_sync(0xffffffffu, cnt, off);
            nA  += __shfl_down_sync(0xffffffffu, nA, off);
            nB  += __shfl_down_sync(0xffffffffu, nB, off);
        }
        if (lane == 0) {
            g_gold[b] = g + endt[__ldg(&tg[cnt - 1])];
            g_nmat[b] = nA + 1 + nB;
        }
        return;
    }

    // ---------------- scan branches (identical to R15) ----------------------
    __shared__ __align__(16) u64 p_sh[2 * 32];

    const int j  = threadIdx.x;
    const int jx = (j < 24) ? j : 23;   // safe index for loads
    const bool active = (j < 24);
    const bool is_fwd = (blockIdx.x < BB);
    const int b = is_fwd ? blockIdx.x : (blockIdx.x - BB);

    const float inv64 = 0.015625f;
    const int c0 = 2 * jx, c1 = 2 * jx + 1;

    u64 E2a[24], E2b[24];
#pragma unroll
    for (int u = 0; u < 24; u++) {
        float a0, a1, b0, b1;
        if (is_fwd) {
            a0 = __expf(__ldg(&trans[(2 * u) * TT + c0])) * inv64;
            a1 = __expf(__ldg(&trans[(2 * u + 1) * TT + c0])) * inv64;
            b0 = __expf(__ldg(&trans[(2 * u) * TT + c1])) * inv64;
            b1 = __expf(__ldg(&trans[(2 * u + 1) * TT + c1])) * inv64;
        } else {
            a0 = __expf(__ldg(&trans[c0 * TT + 2 * u])) * inv64;
            a1 = __expf(__ldg(&trans[c0 * TT + 2 * u + 1])) * inv64;
            b0 = __expf(__ldg(&trans[c1 * TT + 2 * u])) * inv64;
            b1 = __expf(__ldg(&trans[c1 * TT + 2 * u + 1])) * inv64;
        }
        if (!active) { a0 = a1 = 1.0f; b0 = b1 = 1.0f; }
        E2a[u] = pack2(a0, a1);
        E2b[u] = pack2(b0, b1);
    }

    const float* emb = em + (size_t)b * SS * TT;
    const int* mk = mask + (size_t)b * SS;

    u64 q2;
    float r_reg = 1.0f, c_loc = 0.0f;

    float2 ee[8];
    int mm[8];

    auto step = [&](int t, int k, int tn, bool apply_r, bool do_renorm,
                    bool do_pref) {
        const int buf = t & 1;
        p_sh[buf * 32 + j] = q2;

        const float2 e_k = ee[k];
        const int    m_k = mm[k];

        float r_bc = 1.0f;
        if (apply_r) r_bc = __shfl_sync(0xffffffffu, r_reg, 24);

        __syncwarp();

        if (do_pref) {
            ee[k] = *(const float2*)&emb[(size_t)tn * TT + 2 * jx];
            mm[k] = mk[tn];
        }

        const u64* pv = p_sh + buf * 32;
        u64 a0, a1, b0, b1;
        a0 = fmul2(pv[0], E2a[0]);
        b0 = fmul2(pv[12], E2a[12]);
        a1 = fmul2(pv[0], E2b[0]);
        b1 = fmul2(pv[12], E2b[12]);
#pragma unroll
        for (int u = 1; u < 12; u++) {
            a0 = ffma2(pv[u], E2a[u], a0);
            b0 = ffma2(pv[12 + u], E2a[12 + u], b0);
            a1 = ffma2(pv[u], E2b[u], a1);
            b1 = ffma2(pv[12 + u], E2b[12 + u], b1);
        }
        u64 acc0 = fadd2(a0, b0);
        u64 acc1 = fadd2(a1, b1);
        float l0, h0, l1, h1;
        unpack2(acc0, l0, h0);
        unpack2(acc1, l1, h1);
        const float s0 = l0 + h0;       // lane24: s0 = sum(p)
        const float s1 = l1 + h1;

        const float pe0 = __expf(e_k.x);
        const float pe1 = __expf(e_k.y);
        const u64 qn = pack2(s0 * pe0, s1 * pe1);
        q2 = m_k ? qn : q2;

        if (apply_r) q2 = fmul2(q2, pack2(r_bc, r_bc));
        if (do_renorm) {
            r_reg = __fdividef(1.0f, s0);
            c_loc += __logf(s0);
        }
    };

    auto matvec_only = [&](int t) {
        const int buf = t & 1;
        p_sh[buf * 32 + j] = q2;
        __syncwarp();
        const u64* pv = p_sh + buf * 32;
        u64 a0, a1, b0, b1;
        a0 = fmul2(pv[0], E2a[0]);
        b0 = fmul2(pv[12], E2a[12]);
        a1 = fmul2(pv[0], E2b[0]);
        b1 = fmul2(pv[12], E2b[12]);
#pragma unroll
        for (int u = 1; u < 12; u++) {
            a0 = ffma2(pv[u], E2a[u], a0);
            b0 = ffma2(pv[12 + u], E2a[12 + u], b0);
            a1 = ffma2(pv[u], E2b[u], a1);
            b1 = ffma2(pv[12 + u], E2b[12 + u], b1);
        }
        u64 acc0 = fadd2(a0, b0);
        u64 acc1 = fadd2(a1, b1);
        float l0, h0, l1, h1;
        unpack2(acc0, l0, h0);
        unpack2(acc1, l1, h1);
        const float r = __shfl_sync(0xffffffffu, r_reg, 24);
        return make_float2((l0 + h0) * r, (l1 + h1) * r);
    };

    if (is_fwd) {
        q2 = pack2(__expf(startt[c0] + emb[c0]),
                   __expf(startt[c1] + emb[c1]));
#pragma unroll
        for (int k = 0; k < 8; k++) {
            int t = 1 + k;
            ee[k] = *(const float2*)&emb[(size_t)t * TT + 2 * jx];
            mm[k] = mk[t];
        }
        for (int tb = 0; tb < 64; tb++) {
            const int t0 = 1 + tb * 8;
#pragma unroll
            for (int k = 0; k < 8; k++) {
                int t = t0 + k;
                int tn = t + 8; tn = (tn < MID + 1) ? tn : MID;
                step(t, k, tn, k == 0, k == 7, true);
            }
        }
        float2 a = matvec_only(513);
        if (active) *(float2*)&g_alpha[b][2 * j] = a;
        const float cA = __shfl_sync(0xffffffffu, c_loc, 24);
        if (j == 0) g_cA[b] = cA;
    } else {
        const float* eL = &emb[(size_t)(SS - 1) * TT];
        q2 = pack2(__expf(eL[c0] + endt[c0]),
                   __expf(eL[c1] + endt[c1]));
#pragma unroll
        for (int k = 0; k < 8; k++) {
            int t = SS - 2 - k;
            ee[k] = *(const float2*)&emb[(size_t)t * TT + 2 * jx];
            mm[k] = mk[t];
        }
        for (int sb = 0; sb < 63; sb++) {
            const int s0i = sb * 8;
#pragma unroll
            for (int k = 0; k < 8; k++) {
                int s = s0i + k;
                int t = SS - 2 - s;
                int tn = t - 8; tn = (tn > MID + 1) ? tn : (MID + 1);
                step(t, k, tn, k == 0, k == 7, true);
            }
        }
#pragma unroll
        for (int k = 0; k < 6; k++) {
            int t = SS - 2 - (504 + k);          // 518..513
            step(t, k, MID + 1, k == 0, false, false);
        }
        if (active) {
            float ql, qh;
            unpack2(q2, ql, qh);
            *(float2*)&g_beta[b][2 * j] = make_float2(ql, qh);
        }
        const float cB = __shfl_sync(0xffffffffu, c_loc, 24);
        if (j == 0) g_cB[b] = cB;
    }
}

// ---------------------------------------------------------------------------
// Final: thread b computes dot(alpha_b, beta_b), logZ, nll; block-reduce mean.
// All inputs are L2-resident outputs of the previous kernel.
// ---------------------------------------------------------------------------
__global__ void __launch_bounds__(512) crf_final(float* __restrict__ out)
{
    __shared__ float rs[512];
    const int b = threadIdx.x;

    float s = 0.0f;
#pragma unroll
    for (int i = 0; i < TT; i++) s += g_alpha[b][i] * g_beta[b][i];
    const float logZ = g_cA[b] + g_cB[b]
                     + (float)g_nmat[b] * LN64 + __logf(s);
    rs[b] = logZ - g_gold[b];
    __syncthreads();
    for (int off = 256; off > 0; off >>= 1) {
        if (b < off) rs[b] += rs[b + off];
        __syncthreads();
    }
    if (b == 0) out[0] = rs[0] / (float)BB;
}

extern "C" void kernel_launch(void* const* d_in, const int* in_sizes, int n_in,
                              void* d_out, int out_size)
{
    const float* em   = (const float*)d_in[0];
    const float* tr   = (const float*)d_in[1];
    const float* st   = (const float*)d_in[2];
    const float* en   = (const float*)d_in[3];
    const int*   tags = (const int*)d_in[4];
    const int*   mask = (const int*)d_in[5];
    float* out = (float*)d_out;

    crf_fwdbwd<<<3 * BB, 32>>>(em, tr, st, en, tags, mask);
    crf_final<<<1, 512>>>(out);
}

// round 17
// speedup vs baseline: 1.2568x; 1.2568x over previous
#include <cuda_runtime.h>

#define BB 512
#define SS 1024
#define TT 48
#define MID 512
#define LN64 4.1588830833596715f

typedef unsigned long long u64;

__device__ float g_nll[BB];
__device__ float g_alpha[BB][TT];
__device__ float g_beta[BB][TT];
__device__ float g_cA[BB], g_cB[BB];
__device__ unsigned int g_done;     // zero-init; self-resetting counter

__device__ __forceinline__ u64 ffma2(u64 a, u64 b, u64 c) {
    u64 d; asm("fma.rn.f32x2 %0, %1, %2, %3;" : "=l"(d) : "l"(a), "l"(b), "l"(c)); return d;
}
__device__ __forceinline__ u64 fmul2(u64 a, u64 b) {
    u64 d; asm("mul.rn.f32x2 %0, %1, %2;" : "=l"(d) : "l"(a), "l"(b)); return d;
}
__device__ __forceinline__ u64 fadd2(u64 a, u64 b) {
    u64 d; asm("add.rn.f32x2 %0, %1, %2;" : "=l"(d) : "l"(a), "l"(b)); return d;
}
__device__ __forceinline__ u64 pack2(float lo, float hi) {
    u64 d; asm("mov.b64 %0, {%1, %2};" : "=l"(d) : "f"(lo), "f"(hi)); return d;
}
__device__ __forceinline__ void unpack2(u64 v, float& lo, float& hi) {
    asm("mov.b64 {%0, %1}, %2;" : "=f"(lo), "=f"(hi) : "l"(v));
}

// ---------------------------------------------------------------------------
// Warp-per-batch bidirectional scan (validated R15 core, unchanged).
// ---------------------------------------------------------------------------
__global__ void __launch_bounds__(32) crf_fwdbwd(
    const float* __restrict__ em,       // [B,S,T]
    const float* __restrict__ trans,    // [T,T]
    const float* __restrict__ startt,   // [T]
    const float* __restrict__ endt,     // [T]
    const int* __restrict__ mask)       // [B,S] bool as int32
{
    __shared__ __align__(16) u64 p_sh[2 * 32];

    const int j  = threadIdx.x;
    const int jx = (j < 24) ? j : 23;   // safe index for loads
    const bool active = (j < 24);
    const bool is_fwd = (blockIdx.x < BB);
    const int b = is_fwd ? blockIdx.x : (blockIdx.x - BB);

    const float inv64 = 0.015625f;
    const int c0 = 2 * jx, c1 = 2 * jx + 1;

    u64 E2a[24], E2b[24];
#pragma unroll
    for (int u = 0; u < 24; u++) {
        float a0, a1, b0, b1;
        if (is_fwd) {
            a0 = __expf(__ldg(&trans[(2 * u) * TT + c0])) * inv64;
            a1 = __expf(__ldg(&trans[(2 * u + 1) * TT + c0])) * inv64;
            b0 = __expf(__ldg(&trans[(2 * u) * TT + c1])) * inv64;
            b1 = __expf(__ldg(&trans[(2 * u + 1) * TT + c1])) * inv64;
        } else {
            a0 = __expf(__ldg(&trans[c0 * TT + 2 * u])) * inv64;
            a1 = __expf(__ldg(&trans[c0 * TT + 2 * u + 1])) * inv64;
            b0 = __expf(__ldg(&trans[c1 * TT + 2 * u])) * inv64;
            b1 = __expf(__ldg(&trans[c1 * TT + 2 * u + 1])) * inv64;
        }
        if (!active) { a0 = a1 = 1.0f; b0 = b1 = 1.0f; }
        E2a[u] = pack2(a0, a1);
        E2b[u] = pack2(b0, b1);
    }

    const float* emb = em + (size_t)b * SS * TT;
    const int* mk = mask + (size_t)b * SS;

    u64 q2;
    float r_reg = 1.0f, c_loc = 0.0f;

    float2 ee[8];
    int mm[8];

    auto step = [&](int t, int k, int tn, bool apply_r, bool do_renorm,
                    bool do_pref) {
        const int buf = t & 1;
        p_sh[buf * 32 + j] = q2;

        const float2 e_k = ee[k];
        const int    m_k = mm[k];

        float r_bc = 1.0f;
        if (apply_r) r_bc = __shfl_sync(0xffffffffu, r_reg, 24);

        __syncwarp();

        if (do_pref) {
            ee[k] = *(const float2*)&emb[(size_t)tn * TT + 2 * jx];
            mm[k] = mk[tn];
        }

        const u64* pv = p_sh + buf * 32;
        u64 a0, a1, b0, b1;
        a0 = fmul2(pv[0], E2a[0]);
        b0 = fmul2(pv[12], E2a[12]);
        a1 = fmul2(pv[0], E2b[0]);
        b1 = fmul2(pv[12], E2b[12]);
#pragma unroll
        for (int u = 1; u < 12; u++) {
            a0 = ffma2(pv[u], E2a[u], a0);
            b0 = ffma2(pv[12 + u], E2a[12 + u], b0);
            a1 = ffma2(pv[u], E2b[u], a1);
            b1 = ffma2(pv[12 + u], E2b[12 + u], b1);
        }
        u64 acc0 = fadd2(a0, b0);
        u64 acc1 = fadd2(a1, b1);
        float l0, h0, l1, h1;
        unpack2(acc0, l0, h0);
        unpack2(acc1, l1, h1);
        const float s0 = l0 + h0;       // lane24: s0 = sum(p)
        const float s1 = l1 + h1;

        const float pe0 = __expf(e_k.x);
        const float pe1 = __expf(e_k.y);
        const u64 qn = pack2(s0 * pe0, s1 * pe1);
        q2 = m_k ? qn : q2;

        if (apply_r) q2 = fmul2(q2, pack2(r_bc, r_bc));
        if (do_renorm) {
            r_reg = __fdividef(1.0f, s0);
            c_loc += __logf(s0);
        }
    };

    auto matvec_only = [&](int t) {
        const int buf = t & 1;
        p_sh[buf * 32 + j] = q2;
        __syncwarp();
        const u64* pv = p_sh + buf * 32;
        u64 a0, a1, b0, b1;
        a0 = fmul2(pv[0], E2a[0]);
        b0 = fmul2(pv[12], E2a[12]);
        a1 = fmul2(pv[0], E2b[0]);
        b1 = fmul2(pv[12], E2b[12]);
#pragma unroll
        for (int u = 1; u < 12; u++) {
            a0 = ffma2(pv[u], E2a[u], a0);
            b0 = ffma2(pv[12 + u], E2a[12 + u], b0);
            a1 = ffma2(pv[u], E2b[u], a1);
            b1 = ffma2(pv[12 + u], E2b[12 + u], b1);
        }
        u64 acc0 = fadd2(a0, b0);
        u64 acc1 = fadd2(a1, b1);
        float l0, h0, l1, h1;
        unpack2(acc0, l0, h0);
        unpack2(acc1, l1, h1);
        const float r = __shfl_sync(0xffffffffu, r_reg, 24);
        return make_float2((l0 + h0) * r, (l1 + h1) * r);
    };

    if (is_fwd) {
        q2 = pack2(__expf(startt[c0] + emb[c0]),
                   __expf(startt[c1] + emb[c1]));
#pragma unroll
        for (int k = 0; k < 8; k++) {
            int t = 1 + k;
            ee[k] = *(const float2*)&emb[(size_t)t * TT + 2 * jx];
            mm[k] = mk[t];
        }
        for (int tb = 0; tb < 64; tb++) {
            const int t0 = 1 + tb * 8;
#pragma unroll
            for (int k = 0; k < 8; k++) {
                int t = t0 + k;
                int tn = t + 8; tn = (tn < MID + 1) ? tn : MID;
                step(t, k, tn, k == 0, k == 7, true);
            }
        }
        float2 a = matvec_only(513);
        if (active) *(float2*)&g_alpha[b][2 * j] = a;
        const float cA = __shfl_sync(0xffffffffu, c_loc, 24);
        if (j == 0) g_cA[b] = cA;
    } else {
        const float* eL = &emb[(size_t)(SS - 1) * TT];
        q2 = pack2(__expf(eL[c0] + endt[c0]),
                   __expf(eL[c1] + endt[c1]));
#pragma unroll
        for (int k = 0; k < 8; k++) {
            int t = SS - 2 - k;
            ee[k] = *(const float2*)&emb[(size_t)t * TT + 2 * jx];
            mm[k] = mk[t];
        }
        for (int sb = 0; sb < 63; sb++) {
            const int s0i = sb * 8;
#pragma unroll
            for (int k = 0; k < 8; k++) {
                int s = s0i + k;
                int t = SS - 2 - s;
                int tn = t - 8; tn = (tn > MID + 1) ? tn : (MID + 1);
                step(t, k, tn, k == 0, k == 7, true);
            }
        }
#pragma unroll
        for (int k = 0; k < 6; k++) {
            int t = SS - 2 - (504 + k);          // 518..513
            step(t, k, MID + 1, k == 0, false, false);
        }
        if (active) {
            float ql, qh;
            unpack2(q2, ql, qh);
            *(float2*)&g_beta[b][2 * j] = make_float2(ql, qh);
        }
        const float cB = __shfl_sync(0xffffffffu, c_loc, 24);
        if (j == 0) g_cB[b] = cB;
    }
}

// ---------------------------------------------------------------------------
// Combine + fused final reduction. 256 threads/block, branch-free gather so
// ptxas front-batches the loads (high MLP -> BW-bound, not latency-bound).
// Last block (atomic counter after threadfence) does the deterministic
// fixed-order mean reduction; counter self-resets for graph replay.
// ---------------------------------------------------------------------------
__global__ void __launch_bounds__(256) crf_combine(
    const float* __restrict__ em,
    const float* __restrict__ trans,
    const float* __restrict__ startt,
    const float* __restrict__ endt,
    const int* __restrict__ tags,
    const int* __restrict__ mask,
    float* __restrict__ out)
{
    __shared__ float rg[256];
    __shared__ int   rc[256], rn[256];
    __shared__ float dot[TT];
    __shared__ bool  last;

    const int b = blockIdx.x;
    const int tid = threadIdx.x;
    const int* tg = tags + (size_t)b * SS;
    const int* mk = mask + (size_t)b * SS;
    const float* emb = em + (size_t)b * SS * TT;

    if (tid < TT) dot[tid] = g_alpha[b][tid] * g_beta[b][tid];

    // branch-free gather: unconditional loads (always-valid indices),
    // predicated accumulate -> front-batched LDGs, MLP ~8
    float g = 0.0f;
    int cnt = 0, nmat = 0;
#pragma unroll
    for (int it = 0; it < 4; it++) {
        const int t = tid + it * 256;
        const int mt = __ldg(&mk[t]) ? 1 : 0;
        const int tc = __ldg(&tg[t]);
        const int tp = __ldg(&tg[(t > 0) ? (t - 1) : 0]);
        const float ev  = __ldg(&emb[(size_t)t * TT + tc]);
        const float trv = __ldg(&trans[tp * TT + tc]);
        cnt += mt;
        const int inner = (t > 0) ? mt : 0;          // masked non-start term
        g += inner ? (trv + ev) : 0.0f;
        g += (t == 0) ? (startt[tc] + ev) : 0.0f;    // start term
        nmat += (inner && t <= SS - 2) ? 1 : 0;      // matvecs t=1..1022
    }
    rg[tid] = g; rc[tid] = cnt; rn[tid] = nmat;
    __syncthreads();
    for (int off = 128; off > 0; off >>= 1) {
        if (tid < off) {
            rg[tid] += rg[tid + off];
            rc[tid] += rc[tid + off];
            rn[tid] += rn[tid + off];
        }
        __syncthreads();
    }
    if (tid == 0) {
        float s = 0.0f;
#pragma unroll
        for (int i = 0; i < TT; i++) s += dot[i];
        // applied matvecs: masked steps t=1..1022 + 1 transition-only at mid
        const float logZ = g_cA[b] + g_cB[b]
                         + (float)(rn[0] + 1) * LN64 + __logf(s);
        const int len = rc[0] - 1;
        const float gold = rg[0] + endt[__ldg(&tg[len])];
        g_nll[b] = logZ - gold;
        __threadfence();
        const unsigned int ticket = atomicAdd(&g_done, 1u);
        last = (ticket == (unsigned int)(BB - 1));
    }
    __syncthreads();
    if (last) {
        // fixed-order deterministic tree over g_nll
        float v = g_nll[tid] + g_nll[tid + 256];
        rg[tid] = v;
        __syncthreads();
        for (int off = 128; off > 0; off >>= 1) {
            if (tid < off) rg[tid] += rg[tid + off];
            __syncthreads();
        }
        if (tid == 0) {
            out[0] = rg[0] / (float)BB;
            g_done = 0;                 // reset for next graph replay
        }
    }
}

extern "C" void kernel_launch(void* const* d_in, const int* in_sizes, int n_in,
                              void* d_out, int out_size)
{
    const float* em   = (const float*)d_in[0];
    const float* tr   = (const float*)d_in[1];
    const float* st   = (const float*)d_in[2];
    const float* en   = (const float*)d_in[3];
    const int*   tags = (const int*)d_in[4];
    const int*   mask = (const int*)d_in[5];
    float* out = (float*)d_out;

    crf_fwdbwd<<<2 * BB, 32>>>(em, tr, st, en, mask);
    crf_combine<<<BB, 256>>>(em, tr, st, en, tags, mask, out);
}